// round 11
// baseline (speedup 1.0000x reference)
#include <cuda_runtime.h>
#include <cuda_fp16.h>

// Problem constants (fixed by the reference)
#define VV   4096                 // vocab
#define MM   4                    // markov order
#define BB   8
#define LL   2048
#define FAN  (MM * (VV + 1))      // 16388
#define NPOS (BB * LL)            // 16384

#define VC   1024                 // vocab chunk; slab = FAN*VC*2B = 33.5 MB (L2-resident)
#define NCH  (VV / VC)            // 4 chunks

#define NSUB 4                    // subtiles per transpose block (along fan_in)
#define CT   (NSUB * 32)          // 128 fan_in columns per block
#define CMAIN 16384               // fan_in covered by main transpose tiles

// ONE slab, reused across all 4 chunks. Interleaved T(c)/G(c) launches keep it
// L2-resident. Table-0 rows (cc < V+1) carry the fp32 bias folded in before
// fp16 quantization (|w+b| <= 2^-6 -> same quantization scale as w alone).
__device__ __half g_slab[(size_t)FAN * VC];

// ---------------------------------------------------------------------------
// Kernel 1: per-chunk transpose+quantize. W rows [v0, v0+VC) x all FAN cols
//   -> g_slab [FAN][VC] fp16 (bias folded into table 0).
// Proven 4x 32x33 scalar-smem subtile scheme (conflict-free both phases).
// W reads use __ldcs (evict-first) to protect the slab in L2.
// grid = (CMAIN/CT + 1 = 129, VC/32 = 32), block (8,32).
// blockIdx.x == 128 handles the 4 remainder fan rows (16384..16387).
// ---------------------------------------------------------------------------
__global__ __launch_bounds__(256)
void ngram_transpose_chunk(const float* __restrict__ W,
                           const float* __restrict__ bias, int v0) {
    const int tx = threadIdx.x;       // 0..7
    const int ty = threadIdx.y;       // 0..31

    if (blockIdx.x == CMAIN / CT) {
        // Remainder rows cc = 16384..16387 (table 3: no bias) for this slice.
        const int t = ty * 8 + tx;    // 0..255
        if (t < 4 * 32) {
            const int r  = t >> 5;    // 0..3
            const int v  = t & 31;
            const int vl = blockIdx.y * 32 + v;       // local vocab in chunk
            g_slab[(size_t)(CMAIN + r) * VC + vl] =
                __float2half_rn(W[(size_t)(v0 + vl) * FAN + CMAIN + r]);
        }
        return;
    }

    __shared__ float tile[NSUB][32][33];

    const int c0  = blockIdx.x * CT;       // fan_in origin
    const int vl0 = blockIdx.y * 32;       // local vocab origin within chunk

    // Load phase: 4 independent float4 streaming reads, scalar smem writes.
    float4 w4[NSUB];
    const float4* wrow = reinterpret_cast<const float4*>(
        &W[(size_t)(v0 + vl0 + ty) * FAN + c0 + tx * 4]);
    #pragma unroll
    for (int s = 0; s < NSUB; s++)
        w4[s] = __ldcs(wrow + s * 8);      // evict-first: don't pollute L2
    #pragma unroll
    for (int s = 0; s < NSUB; s++) {
        tile[s][ty][tx * 4 + 0] = w4[s].x;
        tile[s][ty][tx * 4 + 1] = w4[s].y;
        tile[s][ty][tx * 4 + 2] = w4[s].z;
        tile[s][ty][tx * 4 + 3] = w4[s].w;
    }
    __syncthreads();

    // Store phase: scalar smem reads, optional bias fold (fp32), cvt to fp16,
    // 8-byte slab writes (normal write-back -> allocate/re-dirty in L2).
    const bool foldblk = (c0 < VV + 1);    // block touches table-0 rows
    float4 bb = make_float4(0.f, 0.f, 0.f, 0.f);
    if (foldblk)
        bb = *reinterpret_cast<const float4*>(&bias[v0 + vl0 + tx * 4]);

    #pragma unroll
    for (int s = 0; s < NSUB; s++) {
        const int cc = c0 + s * 32 + ty;
        float x0 = tile[s][tx * 4 + 0][ty];
        float x1 = tile[s][tx * 4 + 1][ty];
        float x2 = tile[s][tx * 4 + 2][ty];
        float x3 = tile[s][tx * 4 + 3][ty];
        if (foldblk && cc < VV + 1) {      // table 0: fold bias (exact fp32 add)
            x0 += bb.x; x1 += bb.y; x2 += bb.z; x3 += bb.w;
        }
        const __half2 p0 = __floats2half2_rn(x0, x1);
        const __half2 p1 = __floats2half2_rn(x2, x3);
        uint2 o;
        o.x = *reinterpret_cast<const unsigned int*>(&p0);
        o.y = *reinterpret_cast<const unsigned int*>(&p1);
        *reinterpret_cast<uint2*>(&g_slab[(size_t)cc * VC + vl0 + tx * 4]) = o;
    }
}

// ---------------------------------------------------------------------------
// Kernel 2: per-chunk gather-sum, warp-per-position, reading the L2-hot slab.
// grid = NPOS/8 = 2048, block = 256 (8 warps = 8 positions).
// Slim inner loop: 4 iterations of 4 independent LDG.128 + 8 HADD2
// (pairwise fp16 adds) + 8 cvt + 8 FADD + 2 streaming STG.128.
// No bias loads (folded into slab). launch_bounds(256,5) for >=40 warps/SM.
// ---------------------------------------------------------------------------
__global__ __launch_bounds__(256, 5)
void ngram_gather_chunk(const int* __restrict__ idx,
                        float* __restrict__ out, int v0) {
    const int warp = threadIdx.x >> 5;
    const int lane = threadIdx.x & 31;

    const int pos = blockIdx.x * 8 + warp;
    const int b   = pos >> 11;           // / LL
    const int l   = pos & (LL - 1);      // % LL

    const uint4* r0; const uint4* r1; const uint4* r2; const uint4* r3;
    {
        int tok;
        tok = (l >= 3) ? __ldg(&idx[b * LL + l - 3]) : VV;
        r0 = reinterpret_cast<const uint4*>(g_slab + (size_t)(0 * (VV + 1) + tok) * VC);
        tok = (l >= 2) ? __ldg(&idx[b * LL + l - 2]) : VV;
        r1 = reinterpret_cast<const uint4*>(g_slab + (size_t)(1 * (VV + 1) + tok) * VC);
        tok = (l >= 1) ? __ldg(&idx[b * LL + l - 1]) : VV;
        r2 = reinterpret_cast<const uint4*>(g_slab + (size_t)(2 * (VV + 1) + tok) * VC);
        tok = __ldg(&idx[b * LL + l]);
        r3 = reinterpret_cast<const uint4*>(g_slab + (size_t)(3 * (VV + 1) + tok) * VC);
    }

    float4* o4 = reinterpret_cast<float4*>(out + (size_t)pos * VV + v0);

    // VC/8 = 128 uint4 items per slab row / 32 lanes = 4 iterations.
    #pragma unroll
    for (int i = 0; i < VC / 8 / 32; i++) {
        const int j = lane + i * 32;

        const uint4 h0 = r0[j];
        const uint4 h1 = r1[j];
        const uint4 h2 = r2[j];
        const uint4 h3 = r3[j];
        const __half2* q0 = reinterpret_cast<const __half2*>(&h0);
        const __half2* q1 = reinterpret_cast<const __half2*>(&h1);
        const __half2* q2 = reinterpret_cast<const __half2*>(&h2);
        const __half2* q3 = reinterpret_cast<const __half2*>(&h3);

        float4 oA, oB;
        {
            // Pairwise fp16 adds (HADD2), then finish in fp32.
            const float2 a0 = __half22float2(__hadd2(q0[0], q1[0]));
            const float2 b0 = __half22float2(__hadd2(q2[0], q3[0]));
            const float2 a1 = __half22float2(__hadd2(q0[1], q1[1]));
            const float2 b1 = __half22float2(__hadd2(q2[1], q3[1]));
            oA.x = a0.x + b0.x;  oA.y = a0.y + b0.y;
            oA.z = a1.x + b1.x;  oA.w = a1.y + b1.y;
            const float2 a2 = __half22float2(__hadd2(q0[2], q1[2]));
            const float2 b2 = __half22float2(__hadd2(q2[2], q3[2]));
            const float2 a3 = __half22float2(__hadd2(q0[3], q1[3]));
            const float2 b3 = __half22float2(__hadd2(q2[3], q3[3]));
            oB.x = a2.x + b2.x;  oB.y = a2.y + b2.y;
            oB.z = a3.x + b3.x;  oB.w = a3.y + b3.y;
        }
        __stcs(&o4[2 * j],     oA);     // streaming: don't evict the slab
        __stcs(&o4[2 * j + 1], oB);
    }
}

// ---------------------------------------------------------------------------
// Launch: interleaved T(c)/G(c) pairs so the slab round-trips through L2.
// Inputs identified by element count:
//   idx : B*L = 16384 (int32), bias : V = 4096, W : V*FAN (largest)
// ---------------------------------------------------------------------------
extern "C" void kernel_launch(void* const* d_in, const int* in_sizes, int n_in,
                              void* d_out, int out_size) {
    const int*   idx  = nullptr;
    const float* W    = nullptr;
    const float* bias = nullptr;

    for (int i = 0; i < n_in; i++) {
        if (in_sizes[i] == NPOS)      idx  = (const int*)d_in[i];
        else if (in_sizes[i] == VV)   bias = (const float*)d_in[i];
        else                          W    = (const float*)d_in[i];
    }

    dim3 tblock(8, 32);
    dim3 tgrid(CMAIN / CT + 1, VC / 32);      // (129, 32)

    for (int c = 0; c < NCH; c++) {
        ngram_transpose_chunk<<<tgrid, tblock>>>(W, bias, c * VC);
        ngram_gather_chunk<<<NPOS / 8, 256>>>(idx, (float*)d_out, c * VC);
    }
}